// round 1
// baseline (speedup 1.0000x reference)
#include <cuda_runtime.h>
#include <cuda_bf16.h>
#include <math.h>

#define NN 100000
#define EE 600000
#define DD 128
#define LL 5
#define BN_EPS 1e-5f

// ---------------- device scratch (no allocations allowed) ----------------
__device__ float  g_h[(size_t)NN * DD];        // node features
__device__ float  g_agg[(size_t)NN * DD];      // GIN aggregation
__device__ float  g_hid[(size_t)NN * 2 * DD];  // MLP hidden
__device__ double g_sum[DD];
__device__ double g_sumsq[DD];

static __device__ __forceinline__ float4 ld4(const float* p) {
    return *reinterpret_cast<const float4*>(p);
}
static __device__ __forceinline__ void add4(float4& a, const float4 b) {
    a.x += b.x; a.y += b.y; a.z += b.z; a.w += b.w;
}

// ---------------- seed: h = sum of 6 atom-feature embeddings ----------------
// one warp per node, lane handles d = lane*4 .. lane*4+3 (D=128 = 32 lanes * 4)
__global__ void seed_kernel(
    const int* __restrict__ an, const int* __restrict__ fc, const int* __restrict__ ct,
    const int* __restrict__ hy, const int* __restrict__ nh, const int* __restrict__ ar,
    const float* __restrict__ Ean, const float* __restrict__ Efc, const float* __restrict__ Ect,
    const float* __restrict__ Ehy, const float* __restrict__ Enh, const float* __restrict__ Ear)
{
    int w = (blockIdx.x * blockDim.x + threadIdx.x) >> 5;
    if (w >= NN) return;
    int d = (threadIdx.x & 31) * 4;
    float4 v = ld4(Ean + (size_t)an[w] * DD + d);
    add4(v, ld4(Efc + (size_t)fc[w] * DD + d));
    add4(v, ld4(Ect + (size_t)ct[w] * DD + d));
    add4(v, ld4(Ehy + (size_t)hy[w] * DD + d));
    add4(v, ld4(Enh + (size_t)nh[w] * DD + d));
    add4(v, ld4(Ear + (size_t)ar[w] * DD + d));
    *reinterpret_cast<float4*>(g_h + (size_t)w * DD + d) = v;
}

// ---------------- init agg = h + self_vec (self-loop folded analytically) ----
__global__ void init_agg_kernel(
    const float* __restrict__ ec, const float* __restrict__ ea,
    const float* __restrict__ eb, const float* __restrict__ ed,
    const float* __restrict__ es)
{
    int w = (blockIdx.x * blockDim.x + threadIdx.x) >> 5;
    if (w >= NN) return;
    int d = (threadIdx.x & 31) * 4;
    float4 sv = ld4(ec + d);
    add4(sv, ld4(ea + d));
    add4(sv, ld4(eb + d));
    add4(sv, ld4(ed + d));
    add4(sv, ld4(es + d));
    float4 v = ld4(g_h + (size_t)w * DD + d);
    add4(v, sv);
    *reinterpret_cast<float4*>(g_agg + (size_t)w * DD + d) = v;
}

// ---------------- scatter: agg[dst] += h[src] + edge_emb ----------------
// one warp per edge; 4 scalar atomics per lane (compiles to RED.ADD)
__global__ void scatter_kernel(
    const int* __restrict__ src, const int* __restrict__ dst,
    const int* __restrict__ ic, const int* __restrict__ ia,
    const int* __restrict__ bt, const int* __restrict__ bd,
    const int* __restrict__ bs,
    const float* __restrict__ ec, const float* __restrict__ ea,
    const float* __restrict__ eb, const float* __restrict__ ed,
    const float* __restrict__ es)
{
    int e = (blockIdx.x * blockDim.x + threadIdx.x) >> 5;
    if (e >= EE) return;
    int d = (threadIdx.x & 31) * 4;
    int s = src[e], t = dst[e];
    float4 v = ld4(g_h + (size_t)s * DD + d);
    add4(v, ld4(ec + (size_t)ic[e] * DD + d));
    add4(v, ld4(ea + (size_t)ia[e] * DD + d));
    add4(v, ld4(eb + (size_t)bt[e] * DD + d));
    add4(v, ld4(ed + (size_t)bd[e] * DD + d));
    add4(v, ld4(es + (size_t)bs[e] * DD + d));
    float* p = g_agg + (size_t)t * DD + d;
    atomicAdd(p + 0, v.x);
    atomicAdd(p + 1, v.y);
    atomicAdd(p + 2, v.z);
    atomicAdd(p + 3, v.w);
}

// ---------------- SGEMM: C = act(A[M,K] @ B[K,Ncols] + bias) ----------------
// classic 128x128x8 tile, 256 threads, 8x8 per-thread microtile
template <int RELU>
__global__ __launch_bounds__(256) void sgemm_kernel(
    const float* __restrict__ A, const float* __restrict__ B,
    const float* __restrict__ bias, float* __restrict__ C,
    int M, int K, int Ncols)
{
    const int BM = 128, BNt = 128, BK = 8;
    __shared__ float As[BK][BM];
    __shared__ float Bs[BK][BNt];

    int bm = blockIdx.y * BM;
    int bn = blockIdx.x * BNt;
    int tid = threadIdx.x;
    int tx = tid & 15;    // 16 col groups
    int ty = tid >> 4;    // 16 row groups

    float acc[8][8];
#pragma unroll
    for (int i = 0; i < 8; i++)
#pragma unroll
        for (int j = 0; j < 8; j++) acc[i][j] = 0.f;

    int a_m = tid >> 1;          // 0..127
    int a_k = (tid & 1) * 4;     // 0 or 4
    int b_k = tid >> 5;          // 0..7
    int b_n = (tid & 31) * 4;    // 0..124

    for (int k0 = 0; k0 < K; k0 += BK) {
        float4 av = make_float4(0.f, 0.f, 0.f, 0.f);
        int gm = bm + a_m;
        if (gm < M) av = ld4(A + (size_t)gm * K + k0 + a_k);
        As[a_k + 0][a_m] = av.x;
        As[a_k + 1][a_m] = av.y;
        As[a_k + 2][a_m] = av.z;
        As[a_k + 3][a_m] = av.w;
        *reinterpret_cast<float4*>(&Bs[b_k][b_n]) =
            ld4(B + (size_t)(k0 + b_k) * Ncols + bn + b_n);
        __syncthreads();
#pragma unroll
        for (int k = 0; k < BK; k++) {
            float a[8], b[8];
            *reinterpret_cast<float4*>(a)     = *reinterpret_cast<float4*>(&As[k][ty * 8]);
            *reinterpret_cast<float4*>(a + 4) = *reinterpret_cast<float4*>(&As[k][ty * 8 + 4]);
            *reinterpret_cast<float4*>(b)     = *reinterpret_cast<float4*>(&Bs[k][tx * 8]);
            *reinterpret_cast<float4*>(b + 4) = *reinterpret_cast<float4*>(&Bs[k][tx * 8 + 4]);
#pragma unroll
            for (int i = 0; i < 8; i++)
#pragma unroll
                for (int j = 0; j < 8; j++)
                    acc[i][j] += a[i] * b[j];
        }
        __syncthreads();
    }

#pragma unroll
    for (int i = 0; i < 8; i++) {
        int m = bm + ty * 8 + i;
        if (m >= M) continue;
#pragma unroll
        for (int j4 = 0; j4 < 8; j4 += 4) {
            int n = bn + tx * 8 + j4;
            float4 v;
            v.x = acc[i][j4 + 0] + bias[n + 0];
            v.y = acc[i][j4 + 1] + bias[n + 1];
            v.z = acc[i][j4 + 2] + bias[n + 2];
            v.w = acc[i][j4 + 3] + bias[n + 3];
            if (RELU) {
                v.x = fmaxf(v.x, 0.f); v.y = fmaxf(v.y, 0.f);
                v.z = fmaxf(v.z, 0.f); v.w = fmaxf(v.w, 0.f);
            }
            *reinterpret_cast<float4*>(C + (size_t)m * Ncols + n) = v;
        }
    }
}

// ---------------- batch norm ----------------
__global__ void zero_stats_kernel() {
    int d = threadIdx.x;
    if (d < DD) { g_sum[d] = 0.0; g_sumsq[d] = 0.0; }
}

__global__ void bn_stats_kernel(const float* __restrict__ x) {
    __shared__ double ssum[256];
    __shared__ double ssq[256];
    int d = threadIdx.x & (DD - 1);
    double s = 0.0, s2 = 0.0;
    for (int r = blockIdx.x * 2 + (threadIdx.x >> 7); r < NN; r += gridDim.x * 2) {
        float v = x[(size_t)r * DD + d];
        s += (double)v;
        s2 += (double)v * (double)v;
    }
    ssum[threadIdx.x] = s;
    ssq[threadIdx.x] = s2;
    __syncthreads();
    if (threadIdx.x < DD) {
        atomicAdd(&g_sum[d], ssum[threadIdx.x] + ssum[threadIdx.x + DD]);
        atomicAdd(&g_sumsq[d], ssq[threadIdx.x] + ssq[threadIdx.x + DD]);
    }
}

__global__ void bn_apply_kernel(
    const float* __restrict__ gamma, const float* __restrict__ beta,
    const float* __restrict__ x, float* __restrict__ out, int relu)
{
    int i = blockIdx.x * blockDim.x + threadIdx.x;
    if (i >= NN * DD / 4) return;
    int d4 = (i & (DD / 4 - 1)) * 4;
    float4 v = ld4(x + (size_t)i * 4);
    float r[4] = {v.x, v.y, v.z, v.w};
#pragma unroll
    for (int j = 0; j < 4; j++) {
        int d = d4 + j;
        double mean_d = g_sum[d] / (double)NN;
        double var_d = g_sumsq[d] / (double)NN - mean_d * mean_d;
        float mean = (float)mean_d;
        float var = (float)var_d;
        float sc = gamma[d] * rsqrtf(var + BN_EPS);
        float val = sc * (r[j] - mean) + beta[d];
        if (relu) val = fmaxf(val, 0.f);
        r[j] = val;
    }
    *reinterpret_cast<float4*>(out + (size_t)i * 4) = make_float4(r[0], r[1], r[2], r[3]);
}

// ---------------- host launcher ----------------
extern "C" void kernel_launch(void* const* d_in, const int* in_sizes, int n_in,
                              void* d_out, int out_size)
{
    const int* atomic_num      = (const int*)d_in[0];
    const int* formal_charge   = (const int*)d_in[1];
    const int* chiral_tag      = (const int*)d_in[2];
    const int* hybridization   = (const int*)d_in[3];
    const int* num_explicit_hs = (const int*)d_in[4];
    const int* is_aromatic     = (const int*)d_in[5];
    const int* edge_index      = (const int*)d_in[6];   // [2, E]
    const int* is_conjugated   = (const int*)d_in[7];
    const int* edge_is_arom    = (const int*)d_in[8];
    const int* bond_type       = (const int*)d_in[9];
    const int* bond_dir        = (const int*)d_in[10];
    const int* bond_stereo     = (const int*)d_in[11];
    const float* emb_atomic_num      = (const float*)d_in[12];
    const float* emb_formal_charge   = (const float*)d_in[13];
    const float* emb_chiral_tag      = (const float*)d_in[14];
    const float* emb_hybridization   = (const float*)d_in[15];
    const float* emb_num_explicit_hs = (const float*)d_in[16];
    const float* emb_is_aromatic     = (const float*)d_in[17];
    const float* e_conj    = (const float*)d_in[18];  // [5, 3, 128]
    const float* e_arom    = (const float*)d_in[19];  // [5, 3, 128]
    const float* e_btype   = (const float*)d_in[20];  // [5, 23, 128]
    const float* e_bdir    = (const float*)d_in[21];  // [5, 8, 128]
    const float* e_bstereo = (const float*)d_in[22];  // [5, 7, 128]
    const float* mlp_w1 = (const float*)d_in[23];     // [5, 128, 256]
    const float* mlp_b1 = (const float*)d_in[24];     // [5, 256]
    const float* mlp_w2 = (const float*)d_in[25];     // [5, 256, 128]
    const float* mlp_b2 = (const float*)d_in[26];     // [5, 128]
    const float* bn_gamma = (const float*)d_in[27];   // [5, 128]
    const float* bn_beta  = (const float*)d_in[28];   // [5, 128]

    const int* src = edge_index;
    const int* dst = edge_index + EE;

    float* h_ptr;   cudaGetSymbolAddress((void**)&h_ptr, g_h);
    float* agg_ptr; cudaGetSymbolAddress((void**)&agg_ptr, g_agg);
    float* hid_ptr; cudaGetSymbolAddress((void**)&hid_ptr, g_hid);

    const int warp_node_blocks = (NN * 32 + 255) / 256;
    const int warp_edge_blocks = (EE * 32 + 255) / 256;

    seed_kernel<<<warp_node_blocks, 256>>>(
        atomic_num, formal_charge, chiral_tag, hybridization,
        num_explicit_hs, is_aromatic,
        emb_atomic_num, emb_formal_charge, emb_chiral_tag,
        emb_hybridization, emb_num_explicit_hs, emb_is_aromatic);

    for (int l = 0; l < LL; l++) {
        const float* ec = e_conj    + (size_t)l * 3 * DD;
        const float* ea = e_arom    + (size_t)l * 3 * DD;
        const float* eb = e_btype   + (size_t)l * 23 * DD;
        const float* ed = e_bdir    + (size_t)l * 8 * DD;
        const float* es = e_bstereo + (size_t)l * 7 * DD;

        init_agg_kernel<<<warp_node_blocks, 256>>>(ec, ea, eb, ed, es);
        scatter_kernel<<<warp_edge_blocks, 256>>>(
            src, dst, is_conjugated, edge_is_arom, bond_type, bond_dir, bond_stereo,
            ec, ea, eb, ed, es);

        // hid = relu(agg @ W1 + b1) : [N,128] x [128,256]
        {
            dim3 grid(256 / 128, (NN + 127) / 128);
            sgemm_kernel<1><<<grid, 256>>>(
                agg_ptr, mlp_w1 + (size_t)l * DD * 2 * DD,
                mlp_b1 + (size_t)l * 2 * DD, hid_ptr, NN, DD, 2 * DD);
        }
        // h = hid @ W2 + b2 : [N,256] x [256,128]
        {
            dim3 grid(1, (NN + 127) / 128);
            sgemm_kernel<0><<<grid, 256>>>(
                hid_ptr, mlp_w2 + (size_t)l * 2 * DD * DD,
                mlp_b2 + (size_t)l * DD, h_ptr, NN, 2 * DD, DD);
        }

        zero_stats_kernel<<<1, 128>>>();
        bn_stats_kernel<<<512, 256>>>(h_ptr);

        float* out = (l == LL - 1) ? (float*)d_out : h_ptr;
        int relu = (l < LL - 1) ? 1 : 0;
        bn_apply_kernel<<<(NN * DD / 4 + 255) / 256, 256>>>(
            bn_gamma + (size_t)l * DD, bn_beta + (size_t)l * DD,
            h_ptr, out, relu);
    }
}

// round 2
// speedup vs baseline: 2.0545x; 2.0545x over previous
#include <cuda_runtime.h>
#include <cuda_bf16.h>
#include <math.h>

#define NN 100000
#define EE 600000
#define DD 128
#define LL 5
#define BN_EPS 1e-5f
#define COMBO 7392            // 2*2*22*7*6 distinct bond-feature combos
#define NCHUNK ((NN + 1023) / 1024)

// ---------------- device scratch (no allocations allowed) ----------------
__device__ float  g_h[(size_t)NN * DD];
__device__ float  g_agg[(size_t)NN * DD];
__device__ float  g_hid[(size_t)NN * 2 * DD];
__device__ float  g_combo[(size_t)COMBO * DD];
__device__ int    g_offs[NN + 1];
__device__ int    g_cursor[NN];
__device__ int    g_chunksums[NCHUNK];
__device__ int2   g_edge_data[EE];            // (src, combo_idx) in CSR order
__device__ double g_sum[DD];
__device__ double g_sumsq[DD];
__device__ float  g_scale[DD];
__device__ float  g_shift[DD];

static __device__ __forceinline__ float4 ld4(const float* p) {
    return *reinterpret_cast<const float4*>(p);
}
static __device__ __forceinline__ void add4(float4& a, const float4 b) {
    a.x += b.x; a.y += b.y; a.z += b.z; a.w += b.w;
}

// ---------------- seed: h = sum of 6 atom-feature embeddings ----------------
__global__ void seed_kernel(
    const int* __restrict__ an, const int* __restrict__ fc, const int* __restrict__ ct,
    const int* __restrict__ hy, const int* __restrict__ nh, const int* __restrict__ ar,
    const float* __restrict__ Ean, const float* __restrict__ Efc, const float* __restrict__ Ect,
    const float* __restrict__ Ehy, const float* __restrict__ Enh, const float* __restrict__ Ear)
{
    int w = (blockIdx.x * blockDim.x + threadIdx.x) >> 5;
    if (w >= NN) return;
    int d = (threadIdx.x & 31) * 4;
    float4 v = ld4(Ean + (size_t)an[w] * DD + d);
    add4(v, ld4(Efc + (size_t)fc[w] * DD + d));
    add4(v, ld4(Ect + (size_t)ct[w] * DD + d));
    add4(v, ld4(Ehy + (size_t)hy[w] * DD + d));
    add4(v, ld4(Enh + (size_t)nh[w] * DD + d));
    add4(v, ld4(Ear + (size_t)ar[w] * DD + d));
    *reinterpret_cast<float4*>(g_h + (size_t)w * DD + d) = v;
}

// ---------------- CSR build (once per launch; layer-independent) ------------
__global__ void deg_zero_kernel() {
    int i = blockIdx.x * blockDim.x + threadIdx.x;
    if (i < NN) g_cursor[i] = 0;   // reuse cursor as degree counter
}

__global__ void deg_count_kernel(const int* __restrict__ dst) {
    int e = blockIdx.x * blockDim.x + threadIdx.x;
    if (e < EE) atomicAdd(&g_cursor[dst[e]], 1);
}

// per-chunk exclusive scan of degrees (chunk = 1024)
__global__ void scan_chunks_kernel() {
    __shared__ int s[1024];
    int i = blockIdx.x * 1024 + threadIdx.x;
    int v = (i < NN) ? g_cursor[i] : 0;
    s[threadIdx.x] = v;
    __syncthreads();
#pragma unroll
    for (int off = 1; off < 1024; off <<= 1) {
        int x = (threadIdx.x >= off) ? s[threadIdx.x - off] : 0;
        __syncthreads();
        s[threadIdx.x] += x;
        __syncthreads();
    }
    if (i < NN) g_offs[i] = s[threadIdx.x] - v;  // exclusive within chunk
    if (threadIdx.x == 1023) g_chunksums[blockIdx.x] = s[1023];
}

__global__ void scan_sums_kernel() {
    if (threadIdx.x == 0) {
        int acc = 0;
        for (int i = 0; i < NCHUNK; i++) {
            int t = g_chunksums[i];
            g_chunksums[i] = acc;
            acc += t;
        }
    }
}

__global__ void scan_apply_kernel() {
    int i = blockIdx.x * blockDim.x + threadIdx.x;
    if (i < NN) {
        int o = g_offs[i] + g_chunksums[i >> 10];
        g_offs[i] = o;
        g_cursor[i] = o;
    }
    if (i == 0) g_offs[NN] = EE;
}

__global__ void csr_fill_kernel(
    const int* __restrict__ src, const int* __restrict__ dst,
    const int* __restrict__ ic, const int* __restrict__ ia,
    const int* __restrict__ bt, const int* __restrict__ bd,
    const int* __restrict__ bs)
{
    int e = blockIdx.x * blockDim.x + threadIdx.x;
    if (e >= EE) return;
    int pos = atomicAdd(&g_cursor[dst[e]], 1);
    int c = (((ic[e] * 2 + ia[e]) * 22 + bt[e]) * 7 + bd[e]) * 6 + bs[e];
    g_edge_data[pos] = make_int2(src[e], c);
}

// ---------------- per-layer combo table: 7392 x 128 ----------------
__global__ void combo_build_kernel(
    const float* __restrict__ ec, const float* __restrict__ ea,
    const float* __restrict__ eb, const float* __restrict__ ed,
    const float* __restrict__ es)
{
    int w = (blockIdx.x * blockDim.x + threadIdx.x) >> 5;
    if (w >= COMBO) return;
    int d = (threadIdx.x & 31) * 4;
    int c = w;
    int vbs = c % 6; c /= 6;
    int vbd = c % 7; c /= 7;
    int vbt = c % 22; c /= 22;
    int via = c & 1;
    int vic = c >> 1;
    float4 v = ld4(ec + (size_t)vic * DD + d);
    add4(v, ld4(ea + (size_t)via * DD + d));
    add4(v, ld4(eb + (size_t)vbt * DD + d));
    add4(v, ld4(ed + (size_t)vbd * DD + d));
    add4(v, ld4(es + (size_t)vbs * DD + d));
    *reinterpret_cast<float4*>(g_combo + (size_t)w * DD + d) = v;
}

// ---------------- aggregation: pure gather, one warp per node ----------------
// agg[n] = h[n] + combo[0] (self loop) + sum_{e: dst=n} (h[src_e] + combo[c_e])
__global__ void aggregate_kernel() {
    int w = (blockIdx.x * blockDim.x + threadIdx.x) >> 5;
    if (w >= NN) return;
    int d = (threadIdx.x & 31) * 4;
    float4 v = ld4(g_h + (size_t)w * DD + d);
    add4(v, ld4(g_combo + d));     // self-loop = combo index 0
    int beg = g_offs[w], end = g_offs[w + 1];
    for (int i = beg; i < end; i++) {
        int2 ed = g_edge_data[i];
        add4(v, ld4(g_h + (size_t)ed.x * DD + d));
        add4(v, ld4(g_combo + (size_t)ed.y * DD + d));
    }
    *reinterpret_cast<float4*>(g_agg + (size_t)w * DD + d) = v;
}

// ---------------- SGEMM: C = act(A @ B + bias), double-buffered 128x128x8 ----
template <int RELU>
__global__ __launch_bounds__(256) void sgemm_kernel(
    const float* __restrict__ A, const float* __restrict__ B,
    const float* __restrict__ bias, float* __restrict__ C,
    int M, int K, int Ncols)
{
    const int BM = 128, BNt = 128, BK = 8;
    __shared__ float As[2][BK][BM];
    __shared__ float Bs[2][BK][BNt];

    int bm = blockIdx.y * BM;
    int bn = blockIdx.x * BNt;
    int tid = threadIdx.x;
    int tx = tid & 15;
    int ty = tid >> 4;

    float acc[8][8];
#pragma unroll
    for (int i = 0; i < 8; i++)
#pragma unroll
        for (int j = 0; j < 8; j++) acc[i][j] = 0.f;

    int a_m = tid >> 1;
    int a_k = (tid & 1) * 4;
    int b_k = tid >> 5;
    int b_n = (tid & 31) * 4;

    int gm = bm + a_m;
    const float* Ap = A + (size_t)gm * K + a_k;
    const float* Bp = B + (size_t)b_k * Ncols + bn + b_n;
    bool a_ok = (gm < M);

    float4 av = a_ok ? ld4(Ap) : make_float4(0.f, 0.f, 0.f, 0.f);
    float4 bv = ld4(Bp);
    As[0][a_k + 0][a_m] = av.x;
    As[0][a_k + 1][a_m] = av.y;
    As[0][a_k + 2][a_m] = av.z;
    As[0][a_k + 3][a_m] = av.w;
    *reinterpret_cast<float4*>(&Bs[0][b_k][b_n]) = bv;
    __syncthreads();

    int ntiles = K / BK;
    for (int t = 0; t < ntiles; t++) {
        int p = t & 1;
        if (t + 1 < ntiles) {
            av = a_ok ? ld4(Ap + (t + 1) * BK) : make_float4(0.f, 0.f, 0.f, 0.f);
            bv = ld4(Bp + (size_t)(t + 1) * BK * Ncols);
        }
#pragma unroll
        for (int k = 0; k < BK; k++) {
            float a[8], b[8];
            *reinterpret_cast<float4*>(a)     = *reinterpret_cast<float4*>(&As[p][k][ty * 8]);
            *reinterpret_cast<float4*>(a + 4) = *reinterpret_cast<float4*>(&As[p][k][ty * 8 + 4]);
            *reinterpret_cast<float4*>(b)     = *reinterpret_cast<float4*>(&Bs[p][k][tx * 8]);
            *reinterpret_cast<float4*>(b + 4) = *reinterpret_cast<float4*>(&Bs[p][k][tx * 8 + 4]);
#pragma unroll
            for (int i = 0; i < 8; i++)
#pragma unroll
                for (int j = 0; j < 8; j++)
                    acc[i][j] += a[i] * b[j];
        }
        if (t + 1 < ntiles) {
            int q = p ^ 1;
            As[q][a_k + 0][a_m] = av.x;
            As[q][a_k + 1][a_m] = av.y;
            As[q][a_k + 2][a_m] = av.z;
            As[q][a_k + 3][a_m] = av.w;
            *reinterpret_cast<float4*>(&Bs[q][b_k][b_n]) = bv;
            __syncthreads();
        }
    }

#pragma unroll
    for (int i = 0; i < 8; i++) {
        int m = bm + ty * 8 + i;
        if (m >= M) continue;
#pragma unroll
        for (int j4 = 0; j4 < 8; j4 += 4) {
            int n = bn + tx * 8 + j4;
            float4 v;
            v.x = acc[i][j4 + 0] + bias[n + 0];
            v.y = acc[i][j4 + 1] + bias[n + 1];
            v.z = acc[i][j4 + 2] + bias[n + 2];
            v.w = acc[i][j4 + 3] + bias[n + 3];
            if (RELU) {
                v.x = fmaxf(v.x, 0.f); v.y = fmaxf(v.y, 0.f);
                v.z = fmaxf(v.z, 0.f); v.w = fmaxf(v.w, 0.f);
            }
            *reinterpret_cast<float4*>(C + (size_t)m * Ncols + n) = v;
        }
    }
}

// ---------------- batch norm ----------------
__global__ void zero_stats_kernel() {
    int d = threadIdx.x;
    if (d < DD) { g_sum[d] = 0.0; g_sumsq[d] = 0.0; }
}

__global__ void bn_stats_kernel(const float* __restrict__ x) {
    __shared__ double ssum[256];
    __shared__ double ssq[256];
    int d = threadIdx.x & (DD - 1);
    double s = 0.0, s2 = 0.0;
    for (int r = blockIdx.x * 2 + (threadIdx.x >> 7); r < NN; r += gridDim.x * 2) {
        float v = x[(size_t)r * DD + d];
        s += (double)v;
        s2 += (double)v * (double)v;
    }
    ssum[threadIdx.x] = s;
    ssq[threadIdx.x] = s2;
    __syncthreads();
    if (threadIdx.x < DD) {
        atomicAdd(&g_sum[d], ssum[threadIdx.x] + ssum[threadIdx.x + DD]);
        atomicAdd(&g_sumsq[d], ssq[threadIdx.x] + ssq[threadIdx.x + DD]);
    }
}

__global__ void bn_finalize_kernel(
    const float* __restrict__ gamma, const float* __restrict__ beta)
{
    int d = threadIdx.x;
    if (d < DD) {
        double m = g_sum[d] / (double)NN;
        double var = g_sumsq[d] / (double)NN - m * m;
        float sc = gamma[d] * rsqrtf((float)var + BN_EPS);
        g_scale[d] = sc;
        g_shift[d] = beta[d] - sc * (float)m;
    }
}

__global__ void bn_apply_kernel(
    const float* __restrict__ x, float* __restrict__ out, int relu)
{
    int i = blockIdx.x * blockDim.x + threadIdx.x;
    if (i >= NN * DD / 4) return;
    int d = (i & (DD / 4 - 1)) * 4;
    float4 v = ld4(x + (size_t)i * 4);
    float4 sc = ld4(g_scale + d);
    float4 sh = ld4(g_shift + d);
    v.x = fmaf(sc.x, v.x, sh.x);
    v.y = fmaf(sc.y, v.y, sh.y);
    v.z = fmaf(sc.z, v.z, sh.z);
    v.w = fmaf(sc.w, v.w, sh.w);
    if (relu) {
        v.x = fmaxf(v.x, 0.f); v.y = fmaxf(v.y, 0.f);
        v.z = fmaxf(v.z, 0.f); v.w = fmaxf(v.w, 0.f);
    }
    *reinterpret_cast<float4*>(out + (size_t)i * 4) = v;
}

// ---------------- host launcher ----------------
extern "C" void kernel_launch(void* const* d_in, const int* in_sizes, int n_in,
                              void* d_out, int out_size)
{
    const int* atomic_num      = (const int*)d_in[0];
    const int* formal_charge   = (const int*)d_in[1];
    const int* chiral_tag      = (const int*)d_in[2];
    const int* hybridization   = (const int*)d_in[3];
    const int* num_explicit_hs = (const int*)d_in[4];
    const int* is_aromatic     = (const int*)d_in[5];
    const int* edge_index      = (const int*)d_in[6];
    const int* is_conjugated   = (const int*)d_in[7];
    const int* edge_is_arom    = (const int*)d_in[8];
    const int* bond_type       = (const int*)d_in[9];
    const int* bond_dir        = (const int*)d_in[10];
    const int* bond_stereo     = (const int*)d_in[11];
    const float* emb_atomic_num      = (const float*)d_in[12];
    const float* emb_formal_charge   = (const float*)d_in[13];
    const float* emb_chiral_tag      = (const float*)d_in[14];
    const float* emb_hybridization   = (const float*)d_in[15];
    const float* emb_num_explicit_hs = (const float*)d_in[16];
    const float* emb_is_aromatic     = (const float*)d_in[17];
    const float* e_conj    = (const float*)d_in[18];
    const float* e_arom    = (const float*)d_in[19];
    const float* e_btype   = (const float*)d_in[20];
    const float* e_bdir    = (const float*)d_in[21];
    const float* e_bstereo = (const float*)d_in[22];
    const float* mlp_w1 = (const float*)d_in[23];
    const float* mlp_b1 = (const float*)d_in[24];
    const float* mlp_w2 = (const float*)d_in[25];
    const float* mlp_b2 = (const float*)d_in[26];
    const float* bn_gamma = (const float*)d_in[27];
    const float* bn_beta  = (const float*)d_in[28];

    const int* src = edge_index;
    const int* dst = edge_index + EE;

    float* h_ptr;   cudaGetSymbolAddress((void**)&h_ptr, g_h);
    float* agg_ptr; cudaGetSymbolAddress((void**)&agg_ptr, g_agg);
    float* hid_ptr; cudaGetSymbolAddress((void**)&hid_ptr, g_hid);

    const int warp_node_blocks  = (NN * 32 + 255) / 256;
    const int warp_combo_blocks = (COMBO * 32 + 255) / 256;
    const int edge_blocks = (EE + 255) / 256;
    const int node_blocks = (NN + 255) / 256;

    // seed node features
    seed_kernel<<<warp_node_blocks, 256>>>(
        atomic_num, formal_charge, chiral_tag, hybridization,
        num_explicit_hs, is_aromatic,
        emb_atomic_num, emb_formal_charge, emb_chiral_tag,
        emb_hybridization, emb_num_explicit_hs, emb_is_aromatic);

    // CSR build (layer-independent)
    deg_zero_kernel<<<node_blocks, 256>>>();
    deg_count_kernel<<<edge_blocks, 256>>>(dst);
    scan_chunks_kernel<<<NCHUNK, 1024>>>();
    scan_sums_kernel<<<1, 32>>>();
    scan_apply_kernel<<<node_blocks, 256>>>();
    csr_fill_kernel<<<edge_blocks, 256>>>(
        src, dst, is_conjugated, edge_is_arom, bond_type, bond_dir, bond_stereo);

    for (int l = 0; l < LL; l++) {
        combo_build_kernel<<<warp_combo_blocks, 256>>>(
            e_conj    + (size_t)l * 3 * DD,
            e_arom    + (size_t)l * 3 * DD,
            e_btype   + (size_t)l * 23 * DD,
            e_bdir    + (size_t)l * 8 * DD,
            e_bstereo + (size_t)l * 7 * DD);

        aggregate_kernel<<<warp_node_blocks, 256>>>();

        {
            dim3 grid(2, (NN + 127) / 128);
            sgemm_kernel<1><<<grid, 256>>>(
                agg_ptr, mlp_w1 + (size_t)l * DD * 2 * DD,
                mlp_b1 + (size_t)l * 2 * DD, hid_ptr, NN, DD, 2 * DD);
        }
        {
            dim3 grid(1, (NN + 127) / 128);
            sgemm_kernel<0><<<grid, 256>>>(
                hid_ptr, mlp_w2 + (size_t)l * 2 * DD * DD,
                mlp_b2 + (size_t)l * DD, h_ptr, NN, 2 * DD, DD);
        }

        zero_stats_kernel<<<1, 128>>>();
        bn_stats_kernel<<<512, 256>>>(h_ptr);
        bn_finalize_kernel<<<1, 128>>>(
            bn_gamma + (size_t)l * DD, bn_beta + (size_t)l * DD);

        float* out = (l == LL - 1) ? (float*)d_out : h_ptr;
        bn_apply_kernel<<<(NN * DD / 4 + 255) / 256, 256>>>(
            h_ptr, out, (l < LL - 1) ? 1 : 0);
    }
}

// round 4
// speedup vs baseline: 2.3210x; 1.1297x over previous
#include <cuda_runtime.h>
#include <cuda_bf16.h>
#include <math.h>
#include <cstdint>

#define NN 100000
#define EE 600000
#define DD 128
#define LL 5
#define BN_EPS 1e-5f
#define COMBO 7392
#define NCHUNK ((NN + 1023) / 1024)

// ---------------- device scratch ----------------
__device__ float  g_h[(size_t)NN * DD];
__device__ float  g_agg[(size_t)NN * DD];
__device__ float  g_hid[(size_t)NN * 2 * DD];
__device__ float  g_combo[(size_t)COMBO * DD];
__device__ int    g_offs[NN + 1];
__device__ int    g_cursor[NN];
__device__ int    g_chunksums[NCHUNK];
__device__ int2   g_edge_data[EE];
__device__ double g_sum[DD];
__device__ double g_sumsq[DD];
__device__ float  g_scale[DD];
__device__ float  g_shift[DD];

static __device__ __forceinline__ float4 ld4(const float* p) {
    return *reinterpret_cast<const float4*>(p);
}
static __device__ __forceinline__ void add4(float4& a, const float4 b) {
    a.x += b.x; a.y += b.y; a.z += b.z; a.w += b.w;
}

// ================= HMMA (mma.sync) GEMM =================
// C = act(A[M,K] @ W[K,N] + bias), fp32 emulated by bf16x3 split:
//   A = Ah + Al, W = Wh + Wl;  C ~= Ah*Wh + Ah*Wl + Al*Wh
// CTA tile 128x128, BK=32, 8 warps (4 along M x 2 along N), warp tile 32x64.
// Smem rows have 80-byte stride: banks (20*r) mod 32 distinct for r=0..7.

static __device__ __forceinline__ uint32_t smem_u32(const void* p) {
    uint32_t a;
    asm("{ .reg .u64 t; cvta.to.shared.u64 t, %1; cvt.u32.u64 %0, t; }" : "=r"(a) : "l"(p));
    return a;
}
static __device__ __forceinline__ void ldm_x4(uint32_t* r, uint32_t addr) {
    asm volatile("ldmatrix.sync.aligned.m8n8.x4.shared.b16 {%0,%1,%2,%3}, [%4];"
        : "=r"(r[0]), "=r"(r[1]), "=r"(r[2]), "=r"(r[3]) : "r"(addr));
}
static __device__ __forceinline__ void mma_bf16(float* d, const uint32_t* a, const uint32_t* b) {
    asm volatile(
        "mma.sync.aligned.m16n8k16.row.col.f32.bf16.bf16.f32 "
        "{%0,%1,%2,%3}, {%4,%5,%6,%7}, {%8,%9}, {%0,%1,%2,%3};"
        : "+f"(d[0]), "+f"(d[1]), "+f"(d[2]), "+f"(d[3])
        : "r"(a[0]), "r"(a[1]), "r"(a[2]), "r"(a[3]), "r"(b[0]), "r"(b[1]));
}

#define SROW 80                       // smem row stride in bytes (32 bf16 + pad)
#define TILE_B (128 * SROW)           // 10240 bytes per operand tile
#define OFF_AH 0
#define OFF_AL (TILE_B)
#define OFF_BH (2 * TILE_B)
#define OFF_BL (3 * TILE_B)
#define STAGE_B (4 * TILE_B)          // 40960
#define HMMA_SMEM (2 * STAGE_B)       // 81920

union Bf4 { unsigned short u[4]; uint2 v; };

static __device__ __forceinline__ void split4(float4 x, Bf4& hi, Bf4& lo) {
    float xs[4] = {x.x, x.y, x.z, x.w};
#pragma unroll
    for (int j = 0; j < 4; j++) {
        __nv_bfloat16 h = __float2bfloat16(xs[j]);
        float fh = __bfloat162float(h);
        __nv_bfloat16 l = __float2bfloat16(xs[j] - fh);
        hi.u[j] = __bfloat16_as_ushort(h);
        lo.u[j] = __bfloat16_as_ushort(l);
    }
}

template <int N, int K, int RELU>
__global__ __launch_bounds__(256, 2) void hmma_gemm_kernel(
    const float* __restrict__ A, const float* __restrict__ W,
    const float* __restrict__ bias, float* __restrict__ C, int M)
{
    extern __shared__ char smem[];
    const uint32_t sb = smem_u32(smem);
    const int tid = threadIdx.x;
    const int lane = tid & 31;
    const int w = tid >> 5;
    const int wm = w & 3;        // 4 warps along M (32 rows each)
    const int wn = w >> 2;       // 2 warps along N (64 cols each)
    const int bm = blockIdx.y * 128;
    const int bn = blockIdx.x * 128;
    const int NCH = K / 32;

    float acc[2][8][4];
#pragma unroll
    for (int mt = 0; mt < 2; mt++)
#pragma unroll
        for (int nt = 0; nt < 8; nt++)
#pragma unroll
            for (int j = 0; j < 4; j++) acc[mt][nt][j] = 0.f;

    // ---- fill one stage: A[128 x 32] and B^T[128n x 32k], bf16 hi/lo ----
    auto fill = [&](int c, int stg) {
        char* s = smem + stg * STAGE_B;
        const int k0 = c * 32;
        // A: 128 rows x 32 cols fp32 -> 1024 float4, 4 per thread
#pragma unroll
        for (int i = 0; i < 4; i++) {
            int f = tid + i * 256;
            int row = f >> 3;
            int c4 = (f & 7) * 4;
            int gm = bm + row;
            float4 v = (gm < M) ? ld4(A + (size_t)gm * K + k0 + c4)
                                : make_float4(0.f, 0.f, 0.f, 0.f);
            Bf4 hi, lo;
            split4(v, hi, lo);
            *(uint2*)(s + OFF_AH + row * SROW + c4 * 2) = hi.v;
            *(uint2*)(s + OFF_AL + row * SROW + c4 * 2) = lo.v;
        }
        // B: want Bt[n][k] = W[(k0+kk)*N + bn+n]; load coalesced along n
#pragma unroll
        for (int i = 0; i < 4; i++) {
            int f = tid + i * 256;
            int kk = f >> 5;
            int n4 = (f & 31) * 4;
            float4 v = ld4(W + (size_t)(k0 + kk) * N + bn + n4);
            Bf4 hi, lo;
            split4(v, hi, lo);
#pragma unroll
            for (int j = 0; j < 4; j++) {
                *(unsigned short*)(s + OFF_BH + (n4 + j) * SROW + kk * 2) = hi.u[j];
                *(unsigned short*)(s + OFF_BL + (n4 + j) * SROW + kk * 2) = lo.u[j];
            }
        }
    };

    // ---- compute one stage ----
    auto compute = [&](int stg) {
        const uint32_t base = sb + stg * STAGE_B;
        const int q = lane >> 3;                  // ldmatrix quad
#pragma unroll
        for (int ks = 0; ks < 2; ks++) {
            // A fragments (hi & lo) for both m-tiles
            uint32_t a_hi[2][4], a_lo[2][4];
            int arow = wm * 32 + (lane & 7) + ((lane >> 3) & 1) * 8;
            int acol = ks * 16 + (lane >> 4) * 8;
#pragma unroll
            for (int mt = 0; mt < 2; mt++) {
                uint32_t ao = (uint32_t)((arow + mt * 16) * SROW + acol * 2);
                ldm_x4(a_hi[mt], base + OFF_AH + ao);
                ldm_x4(a_lo[mt], base + OFF_AL + ao);
            }
            // B fragments in halves of 4 n-tiles (2 x4 loads per half)
#pragma unroll
            for (int half = 0; half < 2; half++) {
                uint32_t b_hi[4][2], b_lo[4][2];
#pragma unroll
                for (int pr = 0; pr < 2; pr++) {
                    int ntp = half * 4 + pr * 2;          // n-tile pair base
                    int nrow = wn * 64 + (ntp + (q >> 1)) * 8 + (lane & 7);
                    int kcol = ks * 16 + (q & 1) * 8;
                    uint32_t bo = (uint32_t)(nrow * SROW + kcol * 2);
                    uint32_t th[4], tl[4];
                    ldm_x4(th, base + OFF_BH + bo);
                    ldm_x4(tl, base + OFF_BL + bo);
                    b_hi[pr * 2][0] = th[0]; b_hi[pr * 2][1] = th[1];
                    b_hi[pr * 2 + 1][0] = th[2]; b_hi[pr * 2 + 1][1] = th[3];
                    b_lo[pr * 2][0] = tl[0]; b_lo[pr * 2][1] = tl[1];
                    b_lo[pr * 2 + 1][0] = tl[2]; b_lo[pr * 2 + 1][1] = tl[3];
                }
#pragma unroll
                for (int mt = 0; mt < 2; mt++)
#pragma unroll
                    for (int j = 0; j < 4; j++) {
                        int nt = half * 4 + j;
                        mma_bf16(acc[mt][nt], a_hi[mt], b_hi[j]);
                        mma_bf16(acc[mt][nt], a_hi[mt], b_lo[j]);
                        mma_bf16(acc[mt][nt], a_lo[mt], b_hi[j]);
                    }
            }
        }
    };

    fill(0, 0);
    __syncthreads();
    for (int c = 0; c < NCH; c++) {
        if (c + 1 < NCH) fill(c + 1, (c + 1) & 1);
        compute(c & 1);
        __syncthreads();
    }

    // ---- epilogue ----
#pragma unroll
    for (int mt = 0; mt < 2; mt++) {
        int row = bm + wm * 32 + mt * 16 + (lane >> 2);
#pragma unroll
        for (int nt = 0; nt < 8; nt++) {
            int col = bn + wn * 64 + nt * 8 + (lane & 3) * 2;
            float b0 = bias[col], b1 = bias[col + 1];
            float2 v0, v1;
            v0.x = acc[mt][nt][0] + b0; v0.y = acc[mt][nt][1] + b1;
            v1.x = acc[mt][nt][2] + b0; v1.y = acc[mt][nt][3] + b1;
            if (RELU) {
                v0.x = fmaxf(v0.x, 0.f); v0.y = fmaxf(v0.y, 0.f);
                v1.x = fmaxf(v1.x, 0.f); v1.y = fmaxf(v1.y, 0.f);
            }
            if (row < M)     *(float2*)(C + (size_t)row * N + col) = v0;
            if (row + 8 < M) *(float2*)(C + (size_t)(row + 8) * N + col) = v1;
        }
    }
}

// ---------------- seed ----------------
__global__ void seed_kernel(
    const int* __restrict__ an, const int* __restrict__ fc, const int* __restrict__ ct,
    const int* __restrict__ hy, const int* __restrict__ nh, const int* __restrict__ ar,
    const float* __restrict__ Ean, const float* __restrict__ Efc, const float* __restrict__ Ect,
    const float* __restrict__ Ehy, const float* __restrict__ Enh, const float* __restrict__ Ear)
{
    int w = (blockIdx.x * blockDim.x + threadIdx.x) >> 5;
    if (w >= NN) return;
    int d = (threadIdx.x & 31) * 4;
    float4 v = ld4(Ean + (size_t)an[w] * DD + d);
    add4(v, ld4(Efc + (size_t)fc[w] * DD + d));
    add4(v, ld4(Ect + (size_t)ct[w] * DD + d));
    add4(v, ld4(Ehy + (size_t)hy[w] * DD + d));
    add4(v, ld4(Enh + (size_t)nh[w] * DD + d));
    add4(v, ld4(Ear + (size_t)ar[w] * DD + d));
    *reinterpret_cast<float4*>(g_h + (size_t)w * DD + d) = v;
}

// ---------------- CSR build ----------------
__global__ void deg_zero_kernel() {
    int i = blockIdx.x * blockDim.x + threadIdx.x;
    if (i < NN) g_cursor[i] = 0;
}
__global__ void deg_count_kernel(const int* __restrict__ dst) {
    int e = blockIdx.x * blockDim.x + threadIdx.x;
    if (e < EE) atomicAdd(&g_cursor[dst[e]], 1);
}
__global__ void scan_chunks_kernel() {
    __shared__ int s[1024];
    int i = blockIdx.x * 1024 + threadIdx.x;
    int v = (i < NN) ? g_cursor[i] : 0;
    s[threadIdx.x] = v;
    __syncthreads();
#pragma unroll
    for (int off = 1; off < 1024; off <<= 1) {
        int x = (threadIdx.x >= off) ? s[threadIdx.x - off] : 0;
        __syncthreads();
        s[threadIdx.x] += x;
        __syncthreads();
    }
    if (i < NN) g_offs[i] = s[threadIdx.x] - v;
    if (threadIdx.x == 1023) g_chunksums[blockIdx.x] = s[1023];
}
__global__ void scan_sums_kernel() {
    if (threadIdx.x == 0) {
        int acc = 0;
        for (int i = 0; i < NCHUNK; i++) {
            int t = g_chunksums[i];
            g_chunksums[i] = acc;
            acc += t;
        }
    }
}
__global__ void scan_apply_kernel() {
    int i = blockIdx.x * blockDim.x + threadIdx.x;
    if (i < NN) {
        int o = g_offs[i] + g_chunksums[i >> 10];
        g_offs[i] = o;
        g_cursor[i] = o;
    }
    if (i == 0) g_offs[NN] = EE;
}
__global__ void csr_fill_kernel(
    const int* __restrict__ src, const int* __restrict__ dst,
    const int* __restrict__ ic, const int* __restrict__ ia,
    const int* __restrict__ bt, const int* __restrict__ bd,
    const int* __restrict__ bs)
{
    int e = blockIdx.x * blockDim.x + threadIdx.x;
    if (e >= EE) return;
    int pos = atomicAdd(&g_cursor[dst[e]], 1);
    int c = (((ic[e] * 2 + ia[e]) * 22 + bt[e]) * 7 + bd[e]) * 6 + bs[e];
    g_edge_data[pos] = make_int2(src[e], c);
}

// ---------------- combo table ----------------
__global__ void combo_build_kernel(
    const float* __restrict__ ec, const float* __restrict__ ea,
    const float* __restrict__ eb, const float* __restrict__ ed,
    const float* __restrict__ es)
{
    int w = (blockIdx.x * blockDim.x + threadIdx.x) >> 5;
    if (w >= COMBO) return;
    int d = (threadIdx.x & 31) * 4;
    int c = w;
    int vbs = c % 6; c /= 6;
    int vbd = c % 7; c /= 7;
    int vbt = c % 22; c /= 22;
    int via = c & 1;
    int vic = c >> 1;
    float4 v = ld4(ec + (size_t)vic * DD + d);
    add4(v, ld4(ea + (size_t)via * DD + d));
    add4(v, ld4(eb + (size_t)vbt * DD + d));
    add4(v, ld4(ed + (size_t)vbd * DD + d));
    add4(v, ld4(es + (size_t)vbs * DD + d));
    *reinterpret_cast<float4*>(g_combo + (size_t)w * DD + d) = v;
}

// ---------------- aggregation ----------------
__global__ void aggregate_kernel() {
    int w = (blockIdx.x * blockDim.x + threadIdx.x) >> 5;
    if (w >= NN) return;
    int d = (threadIdx.x & 31) * 4;
    float4 v = ld4(g_h + (size_t)w * DD + d);
    add4(v, ld4(g_combo + d));
    int beg = g_offs[w], end = g_offs[w + 1];
    for (int i = beg; i < end; i++) {
        int2 ed = g_edge_data[i];
        add4(v, ld4(g_h + (size_t)ed.x * DD + d));
        add4(v, ld4(g_combo + (size_t)ed.y * DD + d));
    }
    *reinterpret_cast<float4*>(g_agg + (size_t)w * DD + d) = v;
}

// ---------------- batch norm ----------------
__global__ void zero_stats_kernel() {
    int d = threadIdx.x;
    if (d < DD) { g_sum[d] = 0.0; g_sumsq[d] = 0.0; }
}
__global__ void bn_stats_kernel(const float* __restrict__ x) {
    __shared__ double ssum[256];
    __shared__ double ssq[256];
    int d = threadIdx.x & (DD - 1);
    double s = 0.0, s2 = 0.0;
    for (int r = blockIdx.x * 2 + (threadIdx.x >> 7); r < NN; r += gridDim.x * 2) {
        float v = x[(size_t)r * DD + d];
        s += (double)v;
        s2 += (double)v * (double)v;
    }
    ssum[threadIdx.x] = s;
    ssq[threadIdx.x] = s2;
    __syncthreads();
    if (threadIdx.x < DD) {
        atomicAdd(&g_sum[d], ssum[threadIdx.x] + ssum[threadIdx.x + DD]);
        atomicAdd(&g_sumsq[d], ssq[threadIdx.x] + ssq[threadIdx.x + DD]);
    }
}
__global__ void bn_finalize_kernel(
    const float* __restrict__ gamma, const float* __restrict__ beta)
{
    int d = threadIdx.x;
    if (d < DD) {
        double m = g_sum[d] / (double)NN;
        double var = g_sumsq[d] / (double)NN - m * m;
        float sc = gamma[d] * rsqrtf((float)var + BN_EPS);
        g_scale[d] = sc;
        g_shift[d] = beta[d] - sc * (float)m;
    }
}
__global__ void bn_apply_kernel(
    const float* __restrict__ x, float* __restrict__ out, int relu)
{
    int i = blockIdx.x * blockDim.x + threadIdx.x;
    if (i >= NN * DD / 4) return;
    int d = (i & (DD / 4 - 1)) * 4;
    float4 v = ld4(x + (size_t)i * 4);
    float4 sc = ld4(g_scale + d);
    float4 sh = ld4(g_shift + d);
    v.x = fmaf(sc.x, v.x, sh.x);
    v.y = fmaf(sc.y, v.y, sh.y);
    v.z = fmaf(sc.z, v.z, sh.z);
    v.w = fmaf(sc.w, v.w, sh.w);
    if (relu) {
        v.x = fmaxf(v.x, 0.f); v.y = fmaxf(v.y, 0.f);
        v.z = fmaxf(v.z, 0.f); v.w = fmaxf(v.w, 0.f);
    }
    *reinterpret_cast<float4*>(out + (size_t)i * 4) = v;
}

// ---------------- host launcher ----------------
extern "C" void kernel_launch(void* const* d_in, const int* in_sizes, int n_in,
                              void* d_out, int out_size)
{
    const int* atomic_num      = (const int*)d_in[0];
    const int* formal_charge   = (const int*)d_in[1];
    const int* chiral_tag      = (const int*)d_in[2];
    const int* hybridization   = (const int*)d_in[3];
    const int* num_explicit_hs = (const int*)d_in[4];
    const int* is_aromatic     = (const int*)d_in[5];
    const int* edge_index      = (const int*)d_in[6];
    const int* is_conjugated   = (const int*)d_in[7];
    const int* edge_is_arom    = (const int*)d_in[8];
    const int* bond_type       = (const int*)d_in[9];
    const int* bond_dir        = (const int*)d_in[10];
    const int* bond_stereo     = (const int*)d_in[11];
    const float* emb_atomic_num      = (const float*)d_in[12];
    const float* emb_formal_charge   = (const float*)d_in[13];
    const float* emb_chiral_tag      = (const float*)d_in[14];
    const float* emb_hybridization   = (const float*)d_in[15];
    const float* emb_num_explicit_hs = (const float*)d_in[16];
    const float* emb_is_aromatic     = (const float*)d_in[17];
    const float* e_conj    = (const float*)d_in[18];
    const float* e_arom    = (const float*)d_in[19];
    const float* e_btype   = (const float*)d_in[20];
    const float* e_bdir    = (const float*)d_in[21];
    const float* e_bstereo = (const float*)d_in[22];
    const float* mlp_w1 = (const float*)d_in[23];
    const float* mlp_b1 = (const float*)d_in[24];
    const float* mlp_w2 = (const float*)d_in[25];
    const float* mlp_b2 = (const float*)d_in[26];
    const float* bn_gamma = (const float*)d_in[27];
    const float* bn_beta  = (const float*)d_in[28];

    const int* src = edge_index;
    const int* dst = edge_index + EE;

    float* h_ptr;   cudaGetSymbolAddress((void**)&h_ptr, g_h);
    float* agg_ptr; cudaGetSymbolAddress((void**)&agg_ptr, g_agg);
    float* hid_ptr; cudaGetSymbolAddress((void**)&hid_ptr, g_hid);

    cudaFuncSetAttribute(hmma_gemm_kernel<256, 128, 1>,
                         cudaFuncAttributeMaxDynamicSharedMemorySize, HMMA_SMEM);
    cudaFuncSetAttribute(hmma_gemm_kernel<128, 256, 0>,
                         cudaFuncAttributeMaxDynamicSharedMemorySize, HMMA_SMEM);

    const int warp_node_blocks  = (NN * 32 + 255) / 256;
    const int warp_combo_blocks = (COMBO * 32 + 255) / 256;
    const int edge_blocks = (EE + 255) / 256;
    const int node_blocks = (NN + 255) / 256;
    const int mtiles = (NN + 127) / 128;

    seed_kernel<<<warp_node_blocks, 256>>>(
        atomic_num, formal_charge, chiral_tag, hybridization,
        num_explicit_hs, is_aromatic,
        emb_atomic_num, emb_formal_charge, emb_chiral_tag,
        emb_hybridization, emb_num_explicit_hs, emb_is_aromatic);

    deg_zero_kernel<<<node_blocks, 256>>>();
    deg_count_kernel<<<edge_blocks, 256>>>(dst);
    scan_chunks_kernel<<<NCHUNK, 1024>>>();
    scan_sums_kernel<<<1, 32>>>();
    scan_apply_kernel<<<node_blocks, 256>>>();
    csr_fill_kernel<<<edge_blocks, 256>>>(
        src, dst, is_conjugated, edge_is_arom, bond_type, bond_dir, bond_stereo);

    for (int l = 0; l < LL; l++) {
        combo_build_kernel<<<warp_combo_blocks, 256>>>(
            e_conj    + (size_t)l * 3 * DD,
            e_arom    + (size_t)l * 3 * DD,
            e_btype   + (size_t)l * 23 * DD,
            e_bdir    + (size_t)l * 8 * DD,
            e_bstereo + (size_t)l * 7 * DD);

        aggregate_kernel<<<warp_node_blocks, 256>>>();

        {
            dim3 grid(2, mtiles);
            hmma_gemm_kernel<256, 128, 1><<<grid, 256, HMMA_SMEM>>>(
                agg_ptr, mlp_w1 + (size_t)l * DD * 2 * DD,
                mlp_b1 + (size_t)l * 2 * DD, hid_ptr, NN);
        }
        {
            dim3 grid(1, mtiles);
            hmma_gemm_kernel<128, 256, 0><<<grid, 256, HMMA_SMEM>>>(
                hid_ptr, mlp_w2 + (size_t)l * 2 * DD * DD,
                mlp_b2 + (size_t)l * DD, h_ptr, NN);
        }

        zero_stats_kernel<<<1, 128>>>();
        bn_stats_kernel<<<512, 256>>>(h_ptr);
        bn_finalize_kernel<<<1, 128>>>(
            bn_gamma + (size_t)l * DD, bn_beta + (size_t)l * DD);

        float* out = (l == LL - 1) ? (float*)d_out : h_ptr;
        bn_apply_kernel<<<(NN * DD / 4 + 255) / 256, 256>>>(
            h_ptr, out, (l < LL - 1) ? 1 : 0);
    }
}

// round 5
// speedup vs baseline: 2.8114x; 1.2113x over previous
#include <cuda_runtime.h>
#include <cuda_bf16.h>
#include <math.h>
#include <cstdint>

#define NN 100000
#define EE 600000
#define DD 128
#define LL 5
#define BN_EPS 1e-5f
#define COMBO 7392
#define NCHUNK ((NN + 1023) / 1024)

// ---------------- device scratch ----------------
__device__ float  g_h[(size_t)NN * DD];
__device__ __nv_bfloat16 g_agg_h[(size_t)NN * DD];
__device__ __nv_bfloat16 g_agg_l[(size_t)NN * DD];
__device__ __nv_bfloat16 g_hid_h[(size_t)NN * 2 * DD];
__device__ __nv_bfloat16 g_hid_l[(size_t)NN * 2 * DD];
__device__ __nv_bfloat16 g_w1h[DD * 2 * DD];
__device__ __nv_bfloat16 g_w1l[DD * 2 * DD];
__device__ __nv_bfloat16 g_w2h[2 * DD * DD];
__device__ __nv_bfloat16 g_w2l[2 * DD * DD];
__device__ float  g_combo[(size_t)COMBO * DD];
__device__ int    g_offs[NN + 1];
__device__ int    g_cursor[NN];
__device__ int    g_chunksums[NCHUNK];
__device__ int2   g_edge_data[EE];
__device__ double g_sum[DD];
__device__ double g_sumsq[DD];
__device__ float  g_scale[DD];
__device__ float  g_shift[DD];

static __device__ __forceinline__ float4 ld4(const float* p) {
    return *reinterpret_cast<const float4*>(p);
}
static __device__ __forceinline__ void add4(float4& a, const float4 b) {
    a.x += b.x; a.y += b.y; a.z += b.z; a.w += b.w;
}

// ================= HMMA GEMM with pre-split bf16 operands =================
static __device__ __forceinline__ uint32_t smem_u32(const void* p) {
    uint32_t a;
    asm("{ .reg .u64 t; cvta.to.shared.u64 t, %1; cvt.u32.u64 %0, t; }" : "=r"(a) : "l"(p));
    return a;
}
static __device__ __forceinline__ void ldm_x4(uint32_t* r, uint32_t addr) {
    asm volatile("ldmatrix.sync.aligned.m8n8.x4.shared.b16 {%0,%1,%2,%3}, [%4];"
        : "=r"(r[0]), "=r"(r[1]), "=r"(r[2]), "=r"(r[3]) : "r"(addr));
}
static __device__ __forceinline__ void ldm_x4_t(uint32_t* r, uint32_t addr) {
    asm volatile("ldmatrix.sync.aligned.m8n8.x4.trans.shared.b16 {%0,%1,%2,%3}, [%4];"
        : "=r"(r[0]), "=r"(r[1]), "=r"(r[2]), "=r"(r[3]) : "r"(addr));
}
static __device__ __forceinline__ void mma_bf16(float* d, const uint32_t* a, const uint32_t* b) {
    asm volatile(
        "mma.sync.aligned.m16n8k16.row.col.f32.bf16.bf16.f32 "
        "{%0,%1,%2,%3}, {%4,%5,%6,%7}, {%8,%9}, {%0,%1,%2,%3};"
        : "+f"(d[0]), "+f"(d[1]), "+f"(d[2]), "+f"(d[3])
        : "r"(a[0]), "r"(a[1]), "r"(a[2]), "r"(a[3]), "r"(b[0]), "r"(b[1]));
}
static __device__ __forceinline__ void cp16(uint32_t dst, const void* src, int sz) {
    asm volatile("cp.async.cg.shared.global [%0], [%1], 16, %2;"
        :: "r"(dst), "l"(src), "r"(sz) : "memory");
}
static __device__ __forceinline__ void cp_commit() {
    asm volatile("cp.async.commit_group;" ::: "memory");
}
template <int Nk>
static __device__ __forceinline__ void cp_wait() {
    asm volatile("cp.async.wait_group %0;" :: "n"(Nk) : "memory");
}

// smem stage layout (bytes): A rows 80B stride, B rows 272B stride
#define OFF_AH_ 0
#define OFF_AL_ 10240
#define OFF_BH_ 20480
#define OFF_BL_ 29184
#define GS_STAGE 37888
#define OFF_STAT (2 * GS_STAGE)
#define GEMM_SMEM (OFF_STAT + 1024)

static __device__ __forceinline__ uint32_t pack_hi(float v0, float v1) {
    unsigned short h0 = __bfloat16_as_ushort(__float2bfloat16(v0));
    unsigned short h1 = __bfloat16_as_ushort(__float2bfloat16(v1));
    return (uint32_t)h0 | ((uint32_t)h1 << 16);
}
static __device__ __forceinline__ uint32_t pack_lo(float v0, float v1) {
    float f0 = __bfloat162float(__float2bfloat16(v0));
    float f1 = __bfloat162float(__float2bfloat16(v1));
    unsigned short l0 = __bfloat16_as_ushort(__float2bfloat16(v0 - f0));
    unsigned short l1 = __bfloat16_as_ushort(__float2bfloat16(v1 - f1));
    return (uint32_t)l0 | ((uint32_t)l1 << 16);
}

// MODE 0: relu, write bf16 hi/lo (Oh/Ol). MODE 1: no relu, write fp32 Of + column stats.
template <int N, int K, int MODE>
__global__ __launch_bounds__(256, 2) void hsplit_gemm(
    const __nv_bfloat16* __restrict__ Ah, const __nv_bfloat16* __restrict__ Al,
    const __nv_bfloat16* __restrict__ Bh, const __nv_bfloat16* __restrict__ Bl,
    const float* __restrict__ bias,
    __nv_bfloat16* __restrict__ Oh, __nv_bfloat16* __restrict__ Ol,
    float* __restrict__ Of, int M)
{
    extern __shared__ char smem[];
    const uint32_t sb = smem_u32(smem);
    const int tid = threadIdx.x;
    const int lane = tid & 31;
    const int w = tid >> 5;
    const int wm = w & 3;
    const int wn = w >> 2;
    const int bm = blockIdx.y * 128;
    const int bn = blockIdx.x * 128;
    const int NCH = K / 32;

    if (MODE == 1 && tid < 128) {
        *(float*)(smem + OFF_STAT + tid * 4) = 0.f;
        *(float*)(smem + OFF_STAT + 512 + tid * 4) = 0.f;
    }

    float acc[2][8][4];
#pragma unroll
    for (int mt = 0; mt < 2; mt++)
#pragma unroll
        for (int nt = 0; nt < 8; nt++)
#pragma unroll
            for (int j = 0; j < 4; j++) acc[mt][nt][j] = 0.f;

    auto fill = [&](int c, int stg) {
        const uint32_t s = sb + stg * GS_STAGE;
        const int k0 = c * 32;
#pragma unroll
        for (int i = 0; i < 2; i++) {
            int ch = tid + i * 256;
            int row = ch >> 2, part = ch & 3;
            int gm = bm + row;
            int sz = (gm < M) ? 16 : 0;
            int gmc = (gm < M) ? gm : 0;
            size_t go = (size_t)gmc * K + k0 + part * 8;
            cp16(s + OFF_AH_ + row * 80 + part * 16, Ah + go, sz);
            cp16(s + OFF_AL_ + row * 80 + part * 16, Al + go, sz);
        }
#pragma unroll
        for (int i = 0; i < 2; i++) {
            int ch = tid + i * 256;
            int kk = ch >> 4, nc = ch & 15;
            size_t go = (size_t)(k0 + kk) * N + bn + nc * 8;
            cp16(s + OFF_BH_ + kk * 272 + nc * 16, Bh + go, 16);
            cp16(s + OFF_BL_ + kk * 272 + nc * 16, Bl + go, 16);
        }
    };

    auto compute = [&](int stg) {
        const uint32_t base = sb + stg * GS_STAGE;
#pragma unroll
        for (int ks = 0; ks < 2; ks++) {
            uint32_t a_hi[2][4], a_lo[2][4];
            int arow = wm * 32 + (lane & 7) + ((lane >> 3) & 1) * 8;
            int acol = ks * 16 + (lane >> 4) * 8;
#pragma unroll
            for (int mt = 0; mt < 2; mt++) {
                uint32_t ao = (uint32_t)((arow + mt * 16) * 80 + acol * 2);
                ldm_x4(a_hi[mt], base + OFF_AH_ + ao);
                ldm_x4(a_lo[mt], base + OFF_AL_ + ao);
            }
            int krow = ks * 16 + (lane & 7) + ((lane >> 3) & 1) * 8;
#pragma unroll
            for (int g = 0; g < 4; g++) {
                int ncol = wn * 64 + g * 16 + (lane >> 4) * 8;
                uint32_t bo = (uint32_t)(krow * 272 + ncol * 2);
                uint32_t th[4], tl[4];
                ldm_x4_t(th, base + OFF_BH_ + bo);
                ldm_x4_t(tl, base + OFF_BL_ + bo);
#pragma unroll
                for (int mt = 0; mt < 2; mt++) {
                    mma_bf16(acc[mt][2 * g],     a_hi[mt], th);
                    mma_bf16(acc[mt][2 * g],     a_hi[mt], tl);
                    mma_bf16(acc[mt][2 * g],     a_lo[mt], th);
                    mma_bf16(acc[mt][2 * g + 1], a_hi[mt], th + 2);
                    mma_bf16(acc[mt][2 * g + 1], a_hi[mt], tl + 2);
                    mma_bf16(acc[mt][2 * g + 1], a_lo[mt], th + 2);
                }
            }
        }
    };

    fill(0, 0);
    cp_commit();
    if (NCH > 1) { fill(1, 1); cp_commit(); }
    for (int c = 0; c < NCH; c++) {
        if (c + 1 < NCH) cp_wait<1>(); else cp_wait<0>();
        __syncthreads();
        compute(c & 1);
        __syncthreads();
        if (c + 2 < NCH) { fill(c + 2, c & 1); cp_commit(); }
    }

    // ---- epilogue ----
    float* ssum = (float*)(smem + OFF_STAT);
    float* ssq  = (float*)(smem + OFF_STAT + 512);
#pragma unroll
    for (int mt = 0; mt < 2; mt++) {
        int row = bm + wm * 32 + mt * 16 + (lane >> 2);
#pragma unroll
        for (int nt = 0; nt < 8; nt++) {
            int col = bn + wn * 64 + nt * 8 + (lane & 3) * 2;
            float b0 = bias[col], b1 = bias[col + 1];
            float v00 = acc[mt][nt][0] + b0, v01 = acc[mt][nt][1] + b1;
            float v10 = acc[mt][nt][2] + b0, v11 = acc[mt][nt][3] + b1;
            if (MODE == 0) {
                v00 = fmaxf(v00, 0.f); v01 = fmaxf(v01, 0.f);
                v10 = fmaxf(v10, 0.f); v11 = fmaxf(v11, 0.f);
                if (row < M) {
                    *(uint32_t*)(Oh + (size_t)row * N + col) = pack_hi(v00, v01);
                    *(uint32_t*)(Ol + (size_t)row * N + col) = pack_lo(v00, v01);
                }
                if (row + 8 < M) {
                    *(uint32_t*)(Oh + (size_t)(row + 8) * N + col) = pack_hi(v10, v11);
                    *(uint32_t*)(Ol + (size_t)(row + 8) * N + col) = pack_lo(v10, v11);
                }
            } else {
                int lc = col - bn;
                if (row < M) {
                    *(float2*)(Of + (size_t)row * N + col) = make_float2(v00, v01);
                    atomicAdd(&ssum[lc], v00);       atomicAdd(&ssum[lc + 1], v01);
                    atomicAdd(&ssq[lc], v00 * v00);  atomicAdd(&ssq[lc + 1], v01 * v01);
                }
                if (row + 8 < M) {
                    *(float2*)(Of + (size_t)(row + 8) * N + col) = make_float2(v10, v11);
                    atomicAdd(&ssum[lc], v10);       atomicAdd(&ssum[lc + 1], v11);
                    atomicAdd(&ssq[lc], v10 * v10);  atomicAdd(&ssq[lc + 1], v11 * v11);
                }
            }
        }
    }
    if (MODE == 1) {
        __syncthreads();
        if (tid < 128) {
            atomicAdd(&g_sum[tid], (double)ssum[tid]);
            atomicAdd(&g_sumsq[tid], (double)ssq[tid]);
        }
    }
}

// ---------------- W split ----------------
__global__ void wsplit_kernel(const float* __restrict__ w,
                              __nv_bfloat16* __restrict__ wh,
                              __nv_bfloat16* __restrict__ wl, int n)
{
    int i = blockIdx.x * blockDim.x + threadIdx.x;
    if (i >= n) return;
    float x = w[i];
    __nv_bfloat16 h = __float2bfloat16(x);
    wh[i] = h;
    wl[i] = __float2bfloat16(x - __bfloat162float(h));
}

// ---------------- seed ----------------
__global__ void seed_kernel(
    const int* __restrict__ an, const int* __restrict__ fc, const int* __restrict__ ct,
    const int* __restrict__ hy, const int* __restrict__ nh, const int* __restrict__ ar,
    const float* __restrict__ Ean, const float* __restrict__ Efc, const float* __restrict__ Ect,
    const float* __restrict__ Ehy, const float* __restrict__ Enh, const float* __restrict__ Ear)
{
    int w = (blockIdx.x * blockDim.x + threadIdx.x) >> 5;
    if (w >= NN) return;
    int d = (threadIdx.x & 31) * 4;
    float4 v = ld4(Ean + (size_t)an[w] * DD + d);
    add4(v, ld4(Efc + (size_t)fc[w] * DD + d));
    add4(v, ld4(Ect + (size_t)ct[w] * DD + d));
    add4(v, ld4(Ehy + (size_t)hy[w] * DD + d));
    add4(v, ld4(Enh + (size_t)nh[w] * DD + d));
    add4(v, ld4(Ear + (size_t)ar[w] * DD + d));
    *reinterpret_cast<float4*>(g_h + (size_t)w * DD + d) = v;
}

// ---------------- CSR build ----------------
__global__ void deg_zero_kernel() {
    int i = blockIdx.x * blockDim.x + threadIdx.x;
    if (i < NN) g_cursor[i] = 0;
}
__global__ void deg_count_kernel(const int* __restrict__ dst) {
    int e = blockIdx.x * blockDim.x + threadIdx.x;
    if (e < EE) atomicAdd(&g_cursor[dst[e]], 1);
}
__global__ void scan_chunks_kernel() {
    __shared__ int s[1024];
    int i = blockIdx.x * 1024 + threadIdx.x;
    int v = (i < NN) ? g_cursor[i] : 0;
    s[threadIdx.x] = v;
    __syncthreads();
#pragma unroll
    for (int off = 1; off < 1024; off <<= 1) {
        int x = (threadIdx.x >= off) ? s[threadIdx.x - off] : 0;
        __syncthreads();
        s[threadIdx.x] += x;
        __syncthreads();
    }
    if (i < NN) g_offs[i] = s[threadIdx.x] - v;
    if (threadIdx.x == 1023) g_chunksums[blockIdx.x] = s[1023];
}
__global__ void scan_sums_kernel() {
    if (threadIdx.x == 0) {
        int acc = 0;
        for (int i = 0; i < NCHUNK; i++) {
            int t = g_chunksums[i];
            g_chunksums[i] = acc;
            acc += t;
        }
    }
}
__global__ void scan_apply_kernel() {
    int i = blockIdx.x * blockDim.x + threadIdx.x;
    if (i < NN) {
        int o = g_offs[i] + g_chunksums[i >> 10];
        g_offs[i] = o;
        g_cursor[i] = o;
    }
    if (i == 0) g_offs[NN] = EE;
}
__global__ void csr_fill_kernel(
    const int* __restrict__ src, const int* __restrict__ dst,
    const int* __restrict__ ic, const int* __restrict__ ia,
    const int* __restrict__ bt, const int* __restrict__ bd,
    const int* __restrict__ bs)
{
    int e = blockIdx.x * blockDim.x + threadIdx.x;
    if (e >= EE) return;
    int pos = atomicAdd(&g_cursor[dst[e]], 1);
    int c = (((ic[e] * 2 + ia[e]) * 22 + bt[e]) * 7 + bd[e]) * 6 + bs[e];
    g_edge_data[pos] = make_int2(src[e], c);
}

// ---------------- combo table ----------------
__global__ void combo_build_kernel(
    const float* __restrict__ ec, const float* __restrict__ ea,
    const float* __restrict__ eb, const float* __restrict__ ed,
    const float* __restrict__ es)
{
    int w = (blockIdx.x * blockDim.x + threadIdx.x) >> 5;
    if (w >= COMBO) return;
    int d = (threadIdx.x & 31) * 4;
    int c = w;
    int vbs = c % 6; c /= 6;
    int vbd = c % 7; c /= 7;
    int vbt = c % 22; c /= 22;
    int via = c & 1;
    int vic = c >> 1;
    float4 v = ld4(ec + (size_t)vic * DD + d);
    add4(v, ld4(ea + (size_t)via * DD + d));
    add4(v, ld4(eb + (size_t)vbt * DD + d));
    add4(v, ld4(ed + (size_t)vbd * DD + d));
    add4(v, ld4(es + (size_t)vbs * DD + d));
    *reinterpret_cast<float4*>(g_combo + (size_t)w * DD + d) = v;
}

// ---------------- aggregation: gather + bf16 split output ----------------
__global__ void aggregate_kernel() {
    int w = (blockIdx.x * blockDim.x + threadIdx.x) >> 5;
    if (w >= NN) return;
    int d = (threadIdx.x & 31) * 4;
    float4 v = ld4(g_h + (size_t)w * DD + d);
    add4(v, ld4(g_combo + d));
    int beg = g_offs[w], end = g_offs[w + 1];
    for (int i = beg; i < end; i++) {
        int2 ed = g_edge_data[i];
        add4(v, ld4(g_h + (size_t)ed.x * DD + d));
        add4(v, ld4(g_combo + (size_t)ed.y * DD + d));
    }
    uint2 hi, lo;
    hi.x = pack_hi(v.x, v.y); hi.y = pack_hi(v.z, v.w);
    lo.x = pack_lo(v.x, v.y); lo.y = pack_lo(v.z, v.w);
    *(uint2*)(g_agg_h + (size_t)w * DD + d) = hi;
    *(uint2*)(g_agg_l + (size_t)w * DD + d) = lo;
}

// ---------------- batch norm ----------------
__global__ void zero_stats_kernel() {
    int d = threadIdx.x;
    if (d < DD) { g_sum[d] = 0.0; g_sumsq[d] = 0.0; }
}
__global__ void bn_finalize_kernel(
    const float* __restrict__ gamma, const float* __restrict__ beta)
{
    int d = threadIdx.x;
    if (d < DD) {
        double m = g_sum[d] / (double)NN;
        double var = g_sumsq[d] / (double)NN - m * m;
        float sc = gamma[d] * rsqrtf((float)var + BN_EPS);
        g_scale[d] = sc;
        g_shift[d] = beta[d] - sc * (float)m;
    }
}
__global__ void bn_apply_kernel(
    const float* __restrict__ x, float* __restrict__ out, int relu)
{
    int i = blockIdx.x * blockDim.x + threadIdx.x;
    if (i >= NN * DD / 4) return;
    int d = (i & (DD / 4 - 1)) * 4;
    float4 v = ld4(x + (size_t)i * 4);
    float4 sc = ld4(g_scale + d);
    float4 sh = ld4(g_shift + d);
    v.x = fmaf(sc.x, v.x, sh.x);
    v.y = fmaf(sc.y, v.y, sh.y);
    v.z = fmaf(sc.z, v.z, sh.z);
    v.w = fmaf(sc.w, v.w, sh.w);
    if (relu) {
        v.x = fmaxf(v.x, 0.f); v.y = fmaxf(v.y, 0.f);
        v.z = fmaxf(v.z, 0.f); v.w = fmaxf(v.w, 0.f);
    }
    *reinterpret_cast<float4*>(out + (size_t)i * 4) = v;
}

// ---------------- host launcher ----------------
extern "C" void kernel_launch(void* const* d_in, const int* in_sizes, int n_in,
                              void* d_out, int out_size)
{
    const int* atomic_num      = (const int*)d_in[0];
    const int* formal_charge   = (const int*)d_in[1];
    const int* chiral_tag      = (const int*)d_in[2];
    const int* hybridization   = (const int*)d_in[3];
    const int* num_explicit_hs = (const int*)d_in[4];
    const int* is_aromatic     = (const int*)d_in[5];
    const int* edge_index      = (const int*)d_in[6];
    const int* is_conjugated   = (const int*)d_in[7];
    const int* edge_is_arom    = (const int*)d_in[8];
    const int* bond_type       = (const int*)d_in[9];
    const int* bond_dir        = (const int*)d_in[10];
    const int* bond_stereo     = (const int*)d_in[11];
    const float* emb_atomic_num      = (const float*)d_in[12];
    const float* emb_formal_charge   = (const float*)d_in[13];
    const float* emb_chiral_tag      = (const float*)d_in[14];
    const float* emb_hybridization   = (const float*)d_in[15];
    const float* emb_num_explicit_hs = (const float*)d_in[16];
    const float* emb_is_aromatic     = (const float*)d_in[17];
    const float* e_conj    = (const float*)d_in[18];
    const float* e_arom    = (const float*)d_in[19];
    const float* e_btype   = (const float*)d_in[20];
    const float* e_bdir    = (const float*)d_in[21];
    const float* e_bstereo = (const float*)d_in[22];
    const float* mlp_w1 = (const float*)d_in[23];
    const float* mlp_b1 = (const float*)d_in[24];
    const float* mlp_w2 = (const float*)d_in[25];
    const float* mlp_b2 = (const float*)d_in[26];
    const float* bn_gamma = (const float*)d_in[27];
    const float* bn_beta  = (const float*)d_in[28];

    const int* src = edge_index;
    const int* dst = edge_index + EE;

    float* h_ptr; cudaGetSymbolAddress((void**)&h_ptr, g_h);
    __nv_bfloat16 *aggh, *aggl, *hidh, *hidl, *w1h, *w1l, *w2h, *w2l;
    cudaGetSymbolAddress((void**)&aggh, g_agg_h);
    cudaGetSymbolAddress((void**)&aggl, g_agg_l);
    cudaGetSymbolAddress((void**)&hidh, g_hid_h);
    cudaGetSymbolAddress((void**)&hidl, g_hid_l);
    cudaGetSymbolAddress((void**)&w1h, g_w1h);
    cudaGetSymbolAddress((void**)&w1l, g_w1l);
    cudaGetSymbolAddress((void**)&w2h, g_w2h);
    cudaGetSymbolAddress((void**)&w2l, g_w2l);

    cudaFuncSetAttribute(hsplit_gemm<256, 128, 0>,
                         cudaFuncAttributeMaxDynamicSharedMemorySize, GEMM_SMEM);
    cudaFuncSetAttribute(hsplit_gemm<128, 256, 1>,
                         cudaFuncAttributeMaxDynamicSharedMemorySize, GEMM_SMEM);

    const int warp_node_blocks  = (NN * 32 + 255) / 256;
    const int warp_combo_blocks = (COMBO * 32 + 255) / 256;
    const int edge_blocks = (EE + 255) / 256;
    const int node_blocks = (NN + 255) / 256;
    const int mtiles = (NN + 127) / 128;

    seed_kernel<<<warp_node_blocks, 256>>>(
        atomic_num, formal_charge, chiral_tag, hybridization,
        num_explicit_hs, is_aromatic,
        emb_atomic_num, emb_formal_charge, emb_chiral_tag,
        emb_hybridization, emb_num_explicit_hs, emb_is_aromatic);

    deg_zero_kernel<<<node_blocks, 256>>>();
    deg_count_kernel<<<edge_blocks, 256>>>(dst);
    scan_chunks_kernel<<<NCHUNK, 1024>>>();
    scan_sums_kernel<<<1, 32>>>();
    scan_apply_kernel<<<node_blocks, 256>>>();
    csr_fill_kernel<<<edge_blocks, 256>>>(
        src, dst, is_conjugated, edge_is_arom, bond_type, bond_dir, bond_stereo);

    for (int l = 0; l < LL; l++) {
        combo_build_kernel<<<warp_combo_blocks, 256>>>(
            e_conj    + (size_t)l * 3 * DD,
            e_arom    + (size_t)l * 3 * DD,
            e_btype   + (size_t)l * 23 * DD,
            e_bdir    + (size_t)l * 8 * DD,
            e_bstereo + (size_t)l * 7 * DD);

        aggregate_kernel<<<warp_node_blocks, 256>>>();

        wsplit_kernel<<<(DD * 2 * DD + 255) / 256, 256>>>(
            mlp_w1 + (size_t)l * DD * 2 * DD, w1h, w1l, DD * 2 * DD);
        wsplit_kernel<<<(2 * DD * DD + 255) / 256, 256>>>(
            mlp_w2 + (size_t)l * 2 * DD * DD, w2h, w2l, 2 * DD * DD);

        {
            dim3 grid(2, mtiles);
            hsplit_gemm<256, 128, 0><<<grid, 256, GEMM_SMEM>>>(
                aggh, aggl, w1h, w1l,
                mlp_b1 + (size_t)l * 2 * DD, hidh, hidl, nullptr, NN);
        }
        zero_stats_kernel<<<1, 128>>>();
        {
            dim3 grid(1, mtiles);
            hsplit_gemm<128, 256, 1><<<grid, 256, GEMM_SMEM>>>(
                hidh, hidl, w2h, w2l,
                mlp_b2 + (size_t)l * DD, nullptr, nullptr, h_ptr, NN);
        }

        bn_finalize_kernel<<<1, 128>>>(
            bn_gamma + (size_t)l * DD, bn_beta + (size_t)l * DD);

        float* out = (l == LL - 1) ? (float*)d_out : h_ptr;
        bn_apply_kernel<<<(NN * DD / 4 + 255) / 256, 256>>>(
            h_ptr, out, (l < LL - 1) ? 1 : 0);
    }
}